// round 8
// baseline (speedup 1.0000x reference)
#include <cuda_runtime.h>
#include <cuda_bf16.h>
#include <math.h>
#include <stdint.h>

// Problem constants
#define BSZ 256     // batch
#define TT  512     // time steps
#define EE  256     // embedding dim
#define HH  256     // hidden dim
#define KH  512     // E + H
#define G3  768     // 3 * H (z, r, m)
#define MTOT (BSZ * TT)   // 131072 GEMM rows, m = t*256 + b

typedef unsigned long long u64;

// Scratch (device globals: allocation-free rule)
__device__ float        g_bias[G3];
__device__ float2       g_Wzr[HH * HH];              // recurrent z/r interleaved [k][j]
__device__ float        g_Wm2[HH * HH];              // recurrent m [k][j]
__device__ __nv_bfloat16 g_Bhi[G3 * EE];             // B row n=g*256+j, col k: bf16 hi
__device__ __nv_bfloat16 g_Blo[G3 * EE];             // bf16 lo residual
__device__ float        g_Gx[(size_t)MTOT * G3];     // x-part + bias, layout [t][b][3H]

// ---------------------------------------------------------------------------
// PTX helpers
// ---------------------------------------------------------------------------
__device__ __forceinline__ u64 pack2(float lo, float hi) {
    u64 r; asm("mov.b64 %0, {%1, %2};" : "=l"(r) : "f"(lo), "f"(hi)); return r;
}
__device__ __forceinline__ float2 unpack2(u64 v) {
    float2 r; asm("mov.b64 {%0, %1}, %2;" : "=f"(r.x), "=f"(r.y) : "l"(v)); return r;
}
__device__ __forceinline__ void ffma2(u64& d, u64 a, u64 b) {
    asm("fma.rn.f32x2 %0, %1, %2, %0;" : "+l"(d) : "l"(a), "l"(b));
}
__device__ __forceinline__ u64 add2(u64 a, u64 b) {
    u64 r; asm("add.rn.f32x2 %0, %1, %2;" : "=l"(r) : "l"(a), "l"(b)); return r;
}
__device__ __forceinline__ uint32_t smem_u32(const void* p) {
    uint32_t a;
    asm("{ .reg .u64 t; cvta.to.shared.u64 t, %1; cvt.u32.u64 %0, t; }" : "=r"(a) : "l"(p));
    return a;
}
__device__ __forceinline__ uint32_t mapa_u32(uint32_t a, uint32_t rank) {
    uint32_t r; asm("mapa.shared::cluster.u32 %0, %1, %2;" : "=r"(r) : "r"(a), "r"(rank)); return r;
}
__device__ __forceinline__ void st_cluster_b64(uint32_t a, u64 v) {
    asm volatile("st.shared::cluster.b64 [%0], %1;" :: "r"(a), "l"(v) : "memory");
}
#define CLUSTER_SYNC() do { \
    asm volatile("barrier.cluster.arrive.aligned;" ::: "memory"); \
    asm volatile("barrier.cluster.wait.aligned;"   ::: "memory"); \
} while (0)

__device__ __forceinline__ u64 shflx64(u64 v, int m) {
    return (u64)__shfl_xor_sync(0xffffffffu, (unsigned long long)v, m);
}

__device__ __forceinline__ float fast_sigmoid(float x) {
    float e = __expf(-x);
    return __fdividef(1.f, 1.f + e);
}
__device__ __forceinline__ float fast_tanh(float x) {
    float e = __expf(2.f * x);
    return __fdividef(e - 1.f, e + 1.f);
}

// ---- warp-level MMA / cp.async helpers ----
__device__ __forceinline__ void ldsm_x4(uint32_t* r, uint32_t addr) {
    asm volatile("ldmatrix.sync.aligned.m8n8.x4.shared.b16 {%0,%1,%2,%3}, [%4];"
        : "=r"(r[0]), "=r"(r[1]), "=r"(r[2]), "=r"(r[3]) : "r"(addr));
}
__device__ __forceinline__ void ldsm_x2(uint32_t* r, uint32_t addr) {
    asm volatile("ldmatrix.sync.aligned.m8n8.x2.shared.b16 {%0,%1}, [%2];"
        : "=r"(r[0]), "=r"(r[1]) : "r"(addr));
}
__device__ __forceinline__ void mma16816(float* d, const uint32_t* a, const uint32_t* b) {
    asm volatile(
        "mma.sync.aligned.m16n8k16.row.col.f32.bf16.bf16.f32 "
        "{%0,%1,%2,%3}, {%4,%5,%6,%7}, {%8,%9}, {%0,%1,%2,%3};"
        : "+f"(d[0]), "+f"(d[1]), "+f"(d[2]), "+f"(d[3])
        : "r"(a[0]), "r"(a[1]), "r"(a[2]), "r"(a[3]), "r"(b[0]), "r"(b[1]));
}
__device__ __forceinline__ void cp_async16(uint32_t dst, const void* src) {
    asm volatile("cp.async.cg.shared.global [%0], [%1], 16;" :: "r"(dst), "l"(src) : "memory");
}
#define CP_COMMIT() asm volatile("cp.async.commit_group;" ::: "memory")
#define CP_WAIT(n)  asm volatile("cp.async.wait_group %0;" :: "n"(n) : "memory")

// ---------------------------------------------------------------------------
// Kernel 1: bias + recurrent repack + B hi/lo bf16 split
// ---------------------------------------------------------------------------
__global__ void prep_kernel(const float* __restrict__ Wz, const float* __restrict__ bz,
                            const float* __restrict__ Wr, const float* __restrict__ br,
                            const float* __restrict__ Wm, const float* __restrict__ bm) {
    int idx = blockIdx.x * blockDim.x + threadIdx.x;
    if (idx < G3 * EE) {                 // B split: row n = g*256+j, col k
        int n = idx >> 8;
        int k = idx & 255;
        int g = n >> 8;
        int j = n & 255;
        const float* W = (g == 0) ? Wz : (g == 1) ? Wr : Wm;
        float v = W[j * KH + k];
        __nv_bfloat16 hi = __float2bfloat16(v);
        g_Bhi[idx] = hi;
        g_Blo[idx] = __float2bfloat16(v - __bfloat162float(hi));
    }
    if (idx < HH * HH) {                 // recurrent repack (k, j)
        int k = idx >> 8;
        int j = idx & 255;
        g_Wzr[idx] = make_float2(Wz[j * KH + EE + k], Wr[j * KH + EE + k]);
        g_Wm2[idx] = Wm[j * KH + EE + k];
    }
    if (idx < G3) {
        int g  = idx >> 8;
        int jj = idx & 255;
        const float* bb = (g == 0) ? bz : (g == 1) ? br : bm;
        g_bias[idx] = bb[jj];
    }
}

// ---------------------------------------------------------------------------
// Kernel 2: split-bf16 GEMM via mma.sync, cp.async 2-stage pipelined B,
// A converted fp32->hi/lo in-kernel (conv kernel removed).
// 1024 CTAs x 256 thr (8 warps, 4x2 -> warp tile 32M x 64N), M-tile 128.
// 24 chunks: nj(6) x kc(4), chunk = 128n x 64k (hi+lo).
// ---------------------------------------------------------------------------
#define LDA 264                            // A smem row stride (halves)
#define LDB 72                             // B smem row stride (halves): 64 + 8
#define SA_HI 0
#define SA_LO (128 * LDA * 2)              //  67584
#define SB0   (2 * 128 * LDA * 2)          // 135168
#define B_TYPE (128 * LDB * 2)             //  18432 (one of hi/lo per stage)
#define B_STAGE (2 * B_TYPE)               //  36864
#define GEMM_SMEM (SB0 + 2 * B_STAGE)      // 208896

__global__ void __launch_bounds__(256, 1) gemm_mma_kernel(const float* __restrict__ emb) {
    extern __shared__ char smem[];
    uint32_t sbase = smem_u32(smem);
    int tid  = threadIdx.x;
    int warp = tid >> 5;
    int lane = tid & 31;
    int m0 = blockIdx.x * 128;

    int wm = (warp >> 1) * 32;             // warp M offset
    int wn = (warp & 1) * 64;              // warp N offset

    // ---- Issue B chunk c (cp.async, 2 stages) ----
    auto issueB = [&](int c) {
        int nj = c >> 2, kc = c & 3;
        uint32_t stage = sbase + SB0 + (uint32_t)(c & 1) * B_STAGE;
        for (int u = tid; u < 128 * 8; u += 256) {
            int row = u >> 3;
            int cc  = u & 7;
            size_t src = (size_t)(nj * 128 + row) * EE + kc * 64 + cc * 8;
            uint32_t dst = stage + (uint32_t)(row * LDB + cc * 8) * 2;
            cp_async16(dst, g_Bhi + src);
            cp_async16(dst + B_TYPE, g_Blo + src);
        }
        CP_COMMIT();
    };

    issueB(0);

    // ---- Load + convert A tile (128 x 256 fp32 -> hi/lo bf16 smem) ----
    for (int u = tid; u < 128 * 64; u += 256) {
        int row = u >> 6;
        int c4  = u & 63;
        int m = m0 + row;
        int b = m & (BSZ - 1);
        int t = m >> 8;
        float4 v = *(const float4*)(emb + ((size_t)b * TT + t) * EE + c4 * 4);
        __nv_bfloat16 h0 = __float2bfloat16(v.x), h1 = __float2bfloat16(v.y);
        __nv_bfloat16 h2 = __float2bfloat16(v.z), h3 = __float2bfloat16(v.w);
        __nv_bfloat16 hv[4] = {h0, h1, h2, h3};
        __nv_bfloat16 lv[4] = {
            __float2bfloat16(v.x - __bfloat162float(h0)),
            __float2bfloat16(v.y - __bfloat162float(h1)),
            __float2bfloat16(v.z - __bfloat162float(h2)),
            __float2bfloat16(v.w - __bfloat162float(h3))};
        int dst = (row * LDA + c4 * 4) * 2;
        *(uint2*)(smem + SA_HI + dst) = *(const uint2*)hv;
        *(uint2*)(smem + SA_LO + dst) = *(const uint2*)lv;
    }

    // Fragment lane addressing (same formulas as verified R7)
    uint32_t a_row  = (uint32_t)(wm + (lane & 15));
    uint32_t a_coff = (uint32_t)((lane >> 4) * 8);
    uint32_t b_row  = (uint32_t)(wn + (lane & 7));
    uint32_t b_coff = (uint32_t)(((lane >> 3) & 1) * 8);

    float acc[2][8][4];

    for (int c = 0; c < 24; c++) {
        int nj = c >> 2, kc = c & 3;
        if (kc == 0) {
#pragma unroll
            for (int mi = 0; mi < 2; mi++)
#pragma unroll
                for (int ni = 0; ni < 8; ni++)
#pragma unroll
                    for (int q = 0; q < 4; q++) acc[mi][ni][q] = 0.f;
        }

        if (c < 23) { issueB(c + 1); CP_WAIT(1); }
        else        { CP_WAIT(0); }
        __syncthreads();

        uint32_t bstage = sbase + SB0 + (uint32_t)(c & 1) * B_STAGE;
#pragma unroll
        for (int k16 = 0; k16 < 4; k16++) {
            int kA = kc * 64 + k16 * 16;
            int kB = k16 * 16;

            uint32_t aH[2][4], aL[2][4];
#pragma unroll
            for (int mi = 0; mi < 2; mi++) {
                uint32_t off = ((a_row + mi * 16) * LDA + kA + a_coff) * 2;
                ldsm_x4(aH[mi], sbase + SA_HI + off);
                ldsm_x4(aL[mi], sbase + SA_LO + off);
            }
            uint32_t bH[8][2], bL[8][2];
#pragma unroll
            for (int ni = 0; ni < 8; ni++) {
                uint32_t off = ((b_row + ni * 8) * LDB + kB + b_coff) * 2;
                ldsm_x2(bH[ni], bstage + off);
                ldsm_x2(bL[ni], bstage + B_TYPE + off);
            }
#pragma unroll
            for (int mi = 0; mi < 2; mi++)
#pragma unroll
                for (int ni = 0; ni < 8; ni++) {
                    mma16816(acc[mi][ni], aH[mi], bH[ni]);
                    mma16816(acc[mi][ni], aH[mi], bL[ni]);
                    mma16816(acc[mi][ni], aL[mi], bH[ni]);
                }
        }
        __syncthreads();   // all reads of this stage done before it is refilled

        if (kc == 3) {
            // Epilogue: acc + bias -> g_Gx
            int row0 = m0 + wm + (lane >> 2);
#pragma unroll
            for (int mi = 0; mi < 2; mi++) {
#pragma unroll
                for (int ni = 0; ni < 8; ni++) {
                    int n = nj * 128 + wn + ni * 8 + 2 * (lane & 3);
                    float bb0 = __ldg(g_bias + n);
                    float bb1 = __ldg(g_bias + n + 1);
                    float2 v0 = make_float2(acc[mi][ni][0] + bb0, acc[mi][ni][1] + bb1);
                    float2 v1 = make_float2(acc[mi][ni][2] + bb0, acc[mi][ni][3] + bb1);
                    *(float2*)(g_Gx + (size_t)(row0 + mi * 16) * G3 + n)     = v0;
                    *(float2*)(g_Gx + (size_t)(row0 + mi * 16 + 8) * G3 + n) = v1;
                }
            }
        }
    }
}

// ---------------------------------------------------------------------------
// Kernel 3: recurrent, cluster-of-4, shfl-reduced k-split.
// Thread map: jl = tid>>2 (j within slice), ksub = tid&3 (k-slice AND batch-pair).
// The 4 k-slice partials of a given jl live in lanes (4jl..4jl+3) of one warp
// -> reduce with 3 shfl.xor u64 ops, no smem round-trip, no __syncthreads.
// SMEM layouts interleaved for conflict-freedom under this lane geometry:
//   wzr_s[kk*256 + jl*4 + ksub] (u64)   : k = ksub*64+kk, j = crank*64+jl
//   wm_s [kk*256 + jl*4 + ksub] (float)
//   h_s / rh_s: pos(k) = (k&63)*4 + (k>>6), 32B per k (8 batches)
// ---------------------------------------------------------------------------
#define RM_WZR 0
#define RM_WM  131072
#define RM_H   196608
#define RM_RH  204800
#define RM_TOTAL 212992

__global__ void __launch_bounds__(256, 1) __cluster_dims__(4, 1, 1)
gru_rec_kernel(float* __restrict__ out) {
    extern __shared__ char smem_raw[];
    u64*   wzr_s = (u64*)(smem_raw + RM_WZR);
    float* wm_s  = (float*)(smem_raw + RM_WM);
    char*  h_c   = smem_raw + RM_H;
    char*  rh_c  = smem_raw + RM_RH;

    int tid   = threadIdx.x;
    int jl    = tid >> 2;        // 0..63
    int ksub  = tid & 3;         // k-slice / batch-pair
    int crank = blockIdx.x & 3;
    int b0g   = (blockIdx.x >> 2) * 8;
    int jg    = crank * 64 + jl;

    // Stage weights into interleaved layout
    for (int i = tid; i < 64 * 256; i += 256) {
        int kk = i >> 8;
        int jj = (i >> 2) & 63;
        int ks = i & 3;
        int k  = ks * 64 + kk;
        int j2 = crank * 64 + jj;
        wzr_s[i] = *(const u64*)&g_Wzr[k * HH + j2];
        wm_s[i]  = g_Wm2[k * HH + j2];
    }
    for (int i = tid; i < 2048; i += 256) ((float*)h_c)[i] = 0.f;
    __syncthreads();
    CLUSTER_SYNC();

    // DSMEM remote bases (3 remote ranks)
    uint32_t rh_local = smem_u32(rh_c);
    uint32_t h_local  = smem_u32(h_c);
    uint32_t rh_dst[4], h_dst[4];
#pragma unroll
    for (int d = 0; d < 4; d++) {
        rh_dst[d] = mapa_u32(rh_local, (uint32_t)d);
        h_dst[d]  = mapa_u32(h_local,  (uint32_t)d);
    }
    // own (jg, pair) slot: pos(jg) = jl*4 + crank
    uint32_t off_self = (uint32_t)((jl * 4 + crank) * 32 + ksub * 8);

    int b0r = ksub & 1, b1r = (ksub >> 1) & 1;

    for (int t = 0; t < TT; t++) {
        // Gx for this thread's batch pair at jg
        const float* gxb = g_Gx + ((size_t)t * BSZ + b0g + 2 * ksub) * G3 + jg;
        float gz0 = __ldg(gxb);           float gz1 = __ldg(gxb + G3);
        float gr0 = __ldg(gxb + HH);      float gr1 = __ldg(gxb + G3 + HH);
        float gm0 = __ldg(gxb + 2 * HH);  float gm1 = __ldg(gxb + G3 + 2 * HH);

        // ---- Phase A: z/r partial dots over k-slice [64*ksub, 64*ksub+64) ----
        u64 az0 = 0, az1 = 0, az2 = 0, az3 = 0;
        u64 ar0 = 0, ar1 = 0, ar2 = 0, ar3 = 0;
        {
            const u64*  wp = wzr_s + jl * 4 + ksub;
            const char* hp = h_c + ksub * 32;
#pragma unroll 4
            for (int kk = 0; kk < 64; kk++) {
                float2 w = unpack2(wp[kk * 256]);
                u64 wzz = pack2(w.x, w.x);
                u64 wrr = pack2(w.y, w.y);
                ulonglong2 ha = *(const ulonglong2*)(hp + kk * 128);
                ulonglong2 hb = *(const ulonglong2*)(hp + kk * 128 + 16);
                ffma2(az0, wzz, ha.x); ffma2(az1, wzz, ha.y);
                ffma2(az2, wzz, hb.x); ffma2(az3, wzz, hb.y);
                ffma2(ar0, wrr, ha.x); ffma2(ar1, wrr, ha.y);
                ffma2(ar2, wrr, hb.x); ffma2(ar3, wrr, hb.y);
            }
        }
        // ---- shfl reduce-scatter over ksub (each thread keeps its pair) ----
        u64 zL = b0r ? az1 : az0, zLs = b0r ? az0 : az1;
        u64 zH = b0r ? az3 : az2, zHs = b0r ? az2 : az3;
        zL = add2(zL, shflx64(zLs, 1));
        zH = add2(zH, shflx64(zHs, 1));
        u64 zK = b1r ? zH : zL,  zS = b1r ? zL : zH;
        u64 Z  = add2(zK, shflx64(zS, 2));

        u64 rL = b0r ? ar1 : ar0, rLs = b0r ? ar0 : ar1;
        u64 rH = b0r ? ar3 : ar2, rHs = b0r ? ar2 : ar3;
        rL = add2(rL, shflx64(rLs, 1));
        rH = add2(rH, shflx64(rHs, 1));
        u64 rK = b1r ? rH : rL,  rS = b1r ? rL : rH;
        u64 R  = add2(rK, shflx64(rS, 2));

        float2 zf = unpack2(Z), rf = unpack2(R);
        float z0 = fast_sigmoid(zf.x + gz0);
        float z1 = fast_sigmoid(zf.y + gz1);
        float r0 = fast_sigmoid(rf.x + gr0);
        float r1 = fast_sigmoid(rf.y + gr1);
        float2 hold = *(const float2*)(h_c + off_self);
        u64 rhp = pack2(r0 * hold.x, r1 * hold.y);
        *(u64*)(rh_c + off_self) = rhp;           // local copy
#pragma unroll
        for (int d = 0; d < 4; d++)
            if (d != crank) st_cluster_b64(rh_dst[d] + off_self, rhp);
        CLUSTER_SYNC();

        // ---- Phase B: m partial dots ----
        u64 am0 = 0, am1 = 0, am2 = 0, am3 = 0;
        {
            const float* wp = wm_s + jl * 4 + ksub;
            const char*  rp = rh_c + ksub * 32;
#pragma unroll 4
            for (int kk = 0; kk < 64; kk++) {
                float wmv = wp[kk * 256];
                u64 wmm = pack2(wmv, wmv);
                ulonglong2 ra = *(const ulonglong2*)(rp + kk * 128);
                ulonglong2 rb = *(const ulonglong2*)(rp + kk * 128 + 16);
                ffma2(am0, wmm, ra.x); ffma2(am1, wmm, ra.y);
                ffma2(am2, wmm, rb.x); ffma2(am3, wmm, rb.y);
            }
        }
        u64 mL = b0r ? am1 : am0, mLs = b0r ? am0 : am1;
        u64 mH = b0r ? am3 : am2, mHs = b0r ? am2 : am3;
        mL = add2(mL, shflx64(mLs, 1));
        mH = add2(mH, shflx64(mHs, 1));
        u64 mK = b1r ? mH : mL,  mS = b1r ? mL : mH;
        u64 M  = add2(mK, shflx64(mS, 2));

        float2 mf = unpack2(M);
        float hc0 = fast_tanh(mf.x + gm0);
        float hc1 = fast_tanh(mf.y + gm1);
        float hn0 = fmaf(z0, hc0 - hold.x, hold.x);
        float hn1 = fmaf(z1, hc1 - hold.y, hold.y);
        u64 hp2 = pack2(hn0, hn1);
        *(u64*)(h_c + off_self) = hp2;            // local copy
#pragma unroll
        for (int d = 0; d < 4; d++)
            if (d != crank) st_cluster_b64(h_dst[d] + off_self, hp2);

        float* op = out + ((size_t)(b0g + 2 * ksub) * TT + t) * HH + jg;
        op[0]               = hn0;
        op[(size_t)TT * HH] = hn1;
        CLUSTER_SYNC();
    }
}

// ---------------------------------------------------------------------------
// Launch
// ---------------------------------------------------------------------------
extern "C" void kernel_launch(void* const* d_in, const int* in_sizes, int n_in,
                              void* d_out, int out_size) {
    const float* emb = (const float*)d_in[0];
    const float* Wz  = (const float*)d_in[1];
    const float* bz  = (const float*)d_in[2];
    const float* Wr  = (const float*)d_in[3];
    const float* br  = (const float*)d_in[4];
    const float* Wm  = (const float*)d_in[5];
    const float* bm  = (const float*)d_in[6];
    float* out = (float*)d_out;

    cudaFuncSetAttribute(gemm_mma_kernel,
                         cudaFuncAttributeMaxDynamicSharedMemorySize, GEMM_SMEM);
    cudaFuncSetAttribute(gru_rec_kernel,
                         cudaFuncAttributeMaxDynamicSharedMemorySize, RM_TOTAL);

    prep_kernel<<<(G3 * EE + 255) / 256, 256>>>(Wz, bz, Wr, br, Wm, bm);
    gemm_mma_kernel<<<MTOT / 128, 256, GEMM_SMEM>>>(emb);
    gru_rec_kernel<<<128, 256, RM_TOTAL>>>(out);
}

// round 9
// speedup vs baseline: 1.0803x; 1.0803x over previous
#include <cuda_runtime.h>
#include <cuda_bf16.h>
#include <math.h>
#include <stdint.h>

// Problem constants
#define BSZ 256     // batch
#define TT  512     // time steps
#define EE  256     // embedding dim
#define HH  256     // hidden dim
#define KH  512     // E + H
#define G3  768     // 3 * H (z, r, m)
#define MTOT (BSZ * TT)   // 131072 GEMM rows, m = t*256 + b

typedef unsigned long long u64;

// Scratch (device globals: allocation-free rule)
__device__ float        g_bias[G3];
__device__ float2       g_Wzr[HH * HH];              // recurrent z/r interleaved [k][j]
__device__ float        g_Wm2[HH * HH];              // recurrent m [k][j]
__device__ __nv_bfloat16 g_Bhi[G3 * EE];             // B row n=g*256+j, col k: bf16 hi
__device__ __nv_bfloat16 g_Blo[G3 * EE];             // bf16 lo residual
__device__ __nv_bfloat16 g_Ahi[(size_t)MTOT * EE];   // A row m=t*256+b: bf16 hi of emb
__device__ __nv_bfloat16 g_Alo[(size_t)MTOT * EE];
__device__ float        g_Gx[(size_t)MTOT * G3];     // x-part + bias, layout [t][b][3H]

// ---------------------------------------------------------------------------
// PTX helpers
// ---------------------------------------------------------------------------
__device__ __forceinline__ u64 pack2(float lo, float hi) {
    u64 r; asm("mov.b64 %0, {%1, %2};" : "=l"(r) : "f"(lo), "f"(hi)); return r;
}
__device__ __forceinline__ float2 unpack2(u64 v) {
    float2 r; asm("mov.b64 {%0, %1}, %2;" : "=f"(r.x), "=f"(r.y) : "l"(v)); return r;
}
__device__ __forceinline__ void ffma2(u64& d, u64 a, u64 b) {
    asm("fma.rn.f32x2 %0, %1, %2, %0;" : "+l"(d) : "l"(a), "l"(b));
}
__device__ __forceinline__ u64 add2(u64 a, u64 b) {
    u64 r; asm("add.rn.f32x2 %0, %1, %2;" : "=l"(r) : "l"(a), "l"(b)); return r;
}
__device__ __forceinline__ uint32_t smem_u32(const void* p) {
    uint32_t a;
    asm("{ .reg .u64 t; cvta.to.shared.u64 t, %1; cvt.u32.u64 %0, t; }" : "=r"(a) : "l"(p));
    return a;
}
__device__ __forceinline__ uint32_t mapa_u32(uint32_t a, uint32_t rank) {
    uint32_t r; asm("mapa.shared::cluster.u32 %0, %1, %2;" : "=r"(r) : "r"(a), "r"(rank)); return r;
}
__device__ __forceinline__ void st_cluster_b64(uint32_t a, u64 v) {
    asm volatile("st.shared::cluster.b64 [%0], %1;" :: "r"(a), "l"(v) : "memory");
}
#define CLUSTER_SYNC() do { \
    asm volatile("barrier.cluster.arrive.aligned;" ::: "memory"); \
    asm volatile("barrier.cluster.wait.aligned;"   ::: "memory"); \
} while (0)

__device__ __forceinline__ float fast_sigmoid(float x) {
    float e = __expf(-x);
    return __fdividef(1.f, 1.f + e);
}
__device__ __forceinline__ float fast_tanh(float x) {
    float e = __expf(2.f * x);
    return __fdividef(e - 1.f, e + 1.f);
}

// ---- warp-level MMA helpers ----
__device__ __forceinline__ void ldsm_x4(uint32_t* r, uint32_t addr) {
    asm volatile("ldmatrix.sync.aligned.m8n8.x4.shared.b16 {%0,%1,%2,%3}, [%4];"
        : "=r"(r[0]), "=r"(r[1]), "=r"(r[2]), "=r"(r[3]) : "r"(addr));
}
__device__ __forceinline__ void ldsm_x2(uint32_t* r, uint32_t addr) {
    asm volatile("ldmatrix.sync.aligned.m8n8.x2.shared.b16 {%0,%1}, [%2];"
        : "=r"(r[0]), "=r"(r[1]) : "r"(addr));
}
__device__ __forceinline__ void mma16816(float* d, const uint32_t* a, const uint32_t* b) {
    asm volatile(
        "mma.sync.aligned.m16n8k16.row.col.f32.bf16.bf16.f32 "
        "{%0,%1,%2,%3}, {%4,%5,%6,%7}, {%8,%9}, {%0,%1,%2,%3};"
        : "+f"(d[0]), "+f"(d[1]), "+f"(d[2]), "+f"(d[3])
        : "r"(a[0]), "r"(a[1]), "r"(a[2]), "r"(a[3]), "r"(b[0]), "r"(b[1]));
}

// ---------------------------------------------------------------------------
// Kernel 1: bias + recurrent repack + B hi/lo bf16 split
// ---------------------------------------------------------------------------
__global__ void prep_kernel(const float* __restrict__ Wz, const float* __restrict__ bz,
                            const float* __restrict__ Wr, const float* __restrict__ br,
                            const float* __restrict__ Wm, const float* __restrict__ bm) {
    int idx = blockIdx.x * blockDim.x + threadIdx.x;
    if (idx < G3 * EE) {                 // B split: row n = g*256+j, col k
        int n = idx >> 8;
        int k = idx & 255;
        int g = n >> 8;
        int j = n & 255;
        const float* W = (g == 0) ? Wz : (g == 1) ? Wr : Wm;
        float v = W[j * KH + k];
        __nv_bfloat16 hi = __float2bfloat16(v);
        g_Bhi[idx] = hi;
        g_Blo[idx] = __float2bfloat16(v - __bfloat162float(hi));
    }
    if (idx < HH * HH) {                 // recurrent repack (k, j)
        int k = idx >> 8;
        int j = idx & 255;
        g_Wzr[idx] = make_float2(Wz[j * KH + EE + k], Wr[j * KH + EE + k]);
        g_Wm2[idx] = Wm[j * KH + EE + k];
    }
    if (idx < G3) {
        int g  = idx >> 8;
        int jj = idx & 255;
        const float* bb = (g == 0) ? bz : (g == 1) ? br : bm;
        g_bias[idx] = bb[jj];
    }
}

// ---------------------------------------------------------------------------
// Kernel 1b: A hi/lo bf16 split (R7 version, known good)
// ---------------------------------------------------------------------------
__global__ __launch_bounds__(256) void conv_a_kernel(const float* __restrict__ emb) {
    size_t q = (size_t)blockIdx.x * 256 + threadIdx.x;   // quad index
    size_t m = q >> 6;
    int kq = (int)(q & 63) * 4;
    int b = (int)(m & 255);
    int t = (int)(m >> 8);
    float4 v = *(const float4*)(emb + ((size_t)b * TT + t) * EE + kq);
    __nv_bfloat16 h0 = __float2bfloat16(v.x), h1 = __float2bfloat16(v.y);
    __nv_bfloat16 h2 = __float2bfloat16(v.z), h3 = __float2bfloat16(v.w);
    __nv_bfloat16 hv[4] = {h0, h1, h2, h3};
    __nv_bfloat16 lv[4] = {
        __float2bfloat16(v.x - __bfloat162float(h0)),
        __float2bfloat16(v.y - __bfloat162float(h1)),
        __float2bfloat16(v.z - __bfloat162float(h2)),
        __float2bfloat16(v.w - __bfloat162float(h3))};
    *(uint2*)(g_Ahi + m * EE + kq) = *(const uint2*)hv;
    *(uint2*)(g_Alo + m * EE + kq) = *(const uint2*)lv;
}

// ---------------------------------------------------------------------------
// Kernel 2: split-bf16 GEMM via mma.sync — 512 threads, 16 warps (4x4),
// warp tile 32M x 32N. Only change vs R7: more warps + term-ordered MMAs.
// A (128 x K=256, hi+lo) SMEM-resident; B chunks (128n x 128k, hi+lo)
// streamed from L2, 12 rounds.
// ---------------------------------------------------------------------------
#define LDA 264                          // A smem row stride (halves)
#define LDB 136                          // B smem row stride (halves)
#define SA_HI 0
#define SA_LO (128 * LDA * 2)            //  67584
#define SB_HI (2 * 128 * LDA * 2)        // 135168
#define SB_LO (SB_HI + 128 * LDB * 2)    // 169984
#define GEMM_SMEM (SB_LO + 128 * LDB * 2) // 204800

__global__ void __launch_bounds__(512, 1) gemm_mma_kernel() {
    extern __shared__ char smem[];
    uint32_t sbase = smem_u32(smem);
    int tid  = threadIdx.x;
    int warp = tid >> 5;
    int lane = tid & 31;
    int m0 = blockIdx.x * 128;

    int wm = (warp >> 2) * 32;           // warp M offset (0,32,64,96)
    int wn = (warp & 3) * 32;            // warp N offset (0,32,64,96)

    // ---- Load A tile (full K=256, hi+lo) ----
    for (int u = tid; u < 128 * 32; u += 512) {
        int row = u >> 5;
        int c   = u & 31;
        size_t src = (size_t)(m0 + row) * EE + c * 8;
        int dst = (row * LDA + c * 8) * 2;
        *(uint4*)(smem + SA_HI + dst) = *(const uint4*)(g_Ahi + src);
        *(uint4*)(smem + SA_LO + dst) = *(const uint4*)(g_Alo + src);
    }

    // Fragment lane addressing (verified R7 formulas)
    uint32_t a_row  = (uint32_t)(wm + (lane & 15));
    uint32_t a_coff = (uint32_t)((lane >> 4) * 8);
    uint32_t b_row  = (uint32_t)(wn + (lane & 7));
    uint32_t b_coff = (uint32_t)(((lane >> 3) & 1) * 8);

    for (int nj = 0; nj < 6; nj++) {
        float acc[2][4][4];
#pragma unroll
        for (int mi = 0; mi < 2; mi++)
#pragma unroll
            for (int ni = 0; ni < 4; ni++)
#pragma unroll
                for (int q = 0; q < 4; q++) acc[mi][ni][q] = 0.f;

        for (int kt = 0; kt < 2; kt++) {
            __syncthreads();   // prior reads of B done before overwrite
            // ---- Load B chunk (128n x 128k, hi+lo) ----
            for (int u = tid; u < 128 * 16; u += 512) {
                int row = u >> 4;
                int c   = u & 15;
                size_t src = (size_t)(nj * 128 + row) * EE + kt * 128 + c * 8;
                int dst = (row * LDB + c * 8) * 2;
                *(uint4*)(smem + SB_HI + dst) = *(const uint4*)(g_Bhi + src);
                *(uint4*)(smem + SB_LO + dst) = *(const uint4*)(g_Blo + src);
            }
            __syncthreads();

#pragma unroll
            for (int k16 = 0; k16 < 8; k16++) {
                int kA = kt * 128 + k16 * 16;
                int kB = k16 * 16;

                uint32_t aH[2][4], aL[2][4];
#pragma unroll
                for (int mi = 0; mi < 2; mi++) {
                    uint32_t off = ((a_row + mi * 16) * LDA + kA + a_coff) * 2;
                    ldsm_x4(aH[mi], sbase + SA_HI + off);
                    ldsm_x4(aL[mi], sbase + SA_LO + off);
                }
                uint32_t bH[4][2], bL[4][2];
#pragma unroll
                for (int ni = 0; ni < 4; ni++) {
                    uint32_t off = ((b_row + ni * 8) * LDB + kB + b_coff) * 2;
                    ldsm_x2(bH[ni], sbase + SB_HI + off);
                    ldsm_x2(bL[ni], sbase + SB_LO + off);
                }
                // term-ordered: 8 independent MMAs between reuses of each acc
#pragma unroll
                for (int mi = 0; mi < 2; mi++)
#pragma unroll
                    for (int ni = 0; ni < 4; ni++)
                        mma16816(acc[mi][ni], aH[mi], bH[ni]);
#pragma unroll
                for (int mi = 0; mi < 2; mi++)
#pragma unroll
                    for (int ni = 0; ni < 4; ni++)
                        mma16816(acc[mi][ni], aH[mi], bL[ni]);
#pragma unroll
                for (int mi = 0; mi < 2; mi++)
#pragma unroll
                    for (int ni = 0; ni < 4; ni++)
                        mma16816(acc[mi][ni], aL[mi], bH[ni]);
            }
        }

        // ---- Epilogue: acc + bias -> g_Gx ----
        int row0 = m0 + wm + (lane >> 2);
#pragma unroll
        for (int mi = 0; mi < 2; mi++) {
#pragma unroll
            for (int ni = 0; ni < 4; ni++) {
                int n = nj * 128 + wn + ni * 8 + 2 * (lane & 3);
                float bb0 = __ldg(g_bias + n);
                float bb1 = __ldg(g_bias + n + 1);
                float2 v0 = make_float2(acc[mi][ni][0] + bb0, acc[mi][ni][1] + bb1);
                float2 v1 = make_float2(acc[mi][ni][2] + bb0, acc[mi][ni][3] + bb1);
                *(float2*)(g_Gx + (size_t)(row0 + mi * 16) * G3 + n)     = v0;
                *(float2*)(g_Gx + (size_t)(row0 + mi * 16 + 8) * G3 + n) = v1;
            }
        }
    }
}

// ---------------------------------------------------------------------------
// Kernel 3: recurrent part, cluster-of-4 (R5 version, known good)
// ---------------------------------------------------------------------------
#define SM_WZR 0
#define SM_WM  131072
#define SM_H   196608
#define SM_RH  204800
#define SM_P   212992
#define SM_TOTAL 231424

__global__ void __launch_bounds__(256, 1) __cluster_dims__(4, 1, 1)
gru_rec_kernel(float* __restrict__ out) {
    extern __shared__ char smem_raw[];
    float2* wzr_s = (float2*)(smem_raw + SM_WZR);
    float*  wm_s  = (float*)(smem_raw + SM_WM);
    float*  h_s   = (float*)(smem_raw + SM_H);
    float*  rh_s  = (float*)(smem_raw + SM_RH);
    u64*    p_s   = (u64*)(smem_raw + SM_P);

    int tid   = threadIdx.x;
    int jl    = tid & 63;
    int ksub  = tid >> 6;
    int crank = blockIdx.x & 3;
    int b0g   = (blockIdx.x >> 2) * 8;
    int jg    = crank * 64 + jl;

    for (int i = tid; i < HH * 64; i += 256) {
        int k  = i >> 6;
        int j2 = (i & 63) + crank * 64;
        wzr_s[i] = g_Wzr[k * HH + j2];
        wm_s[i]  = g_Wm2[k * HH + j2];
    }
    for (int i = tid; i < HH * 8; i += 256) h_s[i] = 0.f;
    __syncthreads();
    CLUSTER_SYNC();

    uint32_t rh_local = smem_u32(rh_s);
    uint32_t h_local  = smem_u32(h_s);
    uint32_t rh_dst[4], h_dst[4];
#pragma unroll
    for (int d = 0; d < 4; d++) {
        rh_dst[d] = mapa_u32(rh_local, (uint32_t)d);
        h_dst[d]  = mapa_u32(h_local,  (uint32_t)d);
    }
    uint32_t off_pair = (uint32_t)(jg * 8 + 2 * ksub) * 4;

    int k0 = ksub * 64;

    for (int t = 0; t < TT; t++) {
        const float* gxb = g_Gx + ((size_t)t * BSZ + b0g + 2 * ksub) * G3 + jg;
        float gz0 = __ldg(gxb);            float gr0 = __ldg(gxb + HH);
        float gm0 = __ldg(gxb + 2 * HH);
        float gz1 = __ldg(gxb + G3);       float gr1 = __ldg(gxb + G3 + HH);
        float gm1 = __ldg(gxb + G3 + 2 * HH);

        u64 az0 = 0, az1 = 0, az2 = 0, az3 = 0;
        u64 ar0 = 0, ar1 = 0, ar2 = 0, ar3 = 0;
#pragma unroll 4
        for (int kk = 0; kk < 64; kk++) {
            int k = k0 + kk;
            float2 w = wzr_s[k * 64 + jl];
            u64 wzz = pack2(w.x, w.x);
            u64 wrr = pack2(w.y, w.y);
            ulonglong2 ha = *(const ulonglong2*)(h_s + k * 8);
            ulonglong2 hb = *(const ulonglong2*)(h_s + k * 8 + 4);
            ffma2(az0, wzz, ha.x); ffma2(az1, wzz, ha.y);
            ffma2(az2, wzz, hb.x); ffma2(az3, wzz, hb.y);
            ffma2(ar0, wrr, ha.x); ffma2(ar1, wrr, ha.y);
            ffma2(ar2, wrr, hb.x); ffma2(ar3, wrr, hb.y);
        }
        {
            u64* pr = p_s + (ksub * 64 + jl) * 9;
            pr[0] = az0; pr[1] = az1; pr[2] = az2; pr[3] = az3;
            pr[4] = ar0; pr[5] = ar1; pr[6] = ar2; pr[7] = ar3;
        }
        __syncthreads();

        u64 zz = 0, rr = 0;
#pragma unroll
        for (int ks = 0; ks < 4; ks++) {
            const u64* pr = p_s + (ks * 64 + jl) * 9;
            zz = add2(zz, pr[ksub]);
            rr = add2(rr, pr[4 + ksub]);
        }
        float2 zf = unpack2(zz), rf = unpack2(rr);
        float z0 = fast_sigmoid(zf.x + gz0);
        float z1 = fast_sigmoid(zf.y + gz1);
        float r0 = fast_sigmoid(rf.x + gr0);
        float r1 = fast_sigmoid(rf.y + gr1);
        float2 hold = *(const float2*)(h_s + jg * 8 + 2 * ksub);
        u64 rhp = pack2(r0 * hold.x, r1 * hold.y);
#pragma unroll
        for (int d = 0; d < 4; d++) st_cluster_b64(rh_dst[d] + off_pair, rhp);
        CLUSTER_SYNC();

        u64 am0 = 0, am1 = 0, am2 = 0, am3 = 0;
#pragma unroll 4
        for (int kk = 0; kk < 64; kk++) {
            int k = k0 + kk;
            float wm = wm_s[k * 64 + jl];
            u64 wmm = pack2(wm, wm);
            ulonglong2 ra = *(const ulonglong2*)(rh_s + k * 8);
            ulonglong2 rb = *(const ulonglong2*)(rh_s + k * 8 + 4);
            ffma2(am0, wmm, ra.x); ffma2(am1, wmm, ra.y);
            ffma2(am2, wmm, rb.x); ffma2(am3, wmm, rb.y);
        }
        {
            u64* pr = p_s + (ksub * 64 + jl) * 9;
            pr[0] = am0; pr[1] = am1; pr[2] = am2; pr[3] = am3;
        }
        __syncthreads();

        u64 mm = 0;
#pragma unroll
        for (int ks = 0; ks < 4; ks++)
            mm = add2(mm, p_s[(ks * 64 + jl) * 9 + ksub]);
        float2 mf = unpack2(mm);
        float hc0 = fast_tanh(mf.x + gm0);
        float hc1 = fast_tanh(mf.y + gm1);
        float hn0 = fmaf(z0, hc0 - hold.x, hold.x);
        float hn1 = fmaf(z1, hc1 - hold.y, hold.y);
        u64 hp = pack2(hn0, hn1);
#pragma unroll
        for (int d = 0; d < 4; d++) st_cluster_b64(h_dst[d] + off_pair, hp);

        float* op = out + ((size_t)(b0g + 2 * ksub) * TT + t) * HH + jg;
        op[0]               = hn0;
        op[(size_t)TT * HH] = hn1;
        CLUSTER_SYNC();
    }
}

// ---------------------------------------------------------------------------
// Launch
// ---------------------------------------------------------------------------
extern "C" void kernel_launch(void* const* d_in, const int* in_sizes, int n_in,
                              void* d_out, int out_size) {
    const float* emb = (const float*)d_in[0];
    const float* Wz  = (const float*)d_in[1];
    const float* bz  = (const float*)d_in[2];
    const float* Wr  = (const float*)d_in[3];
    const float* br  = (const float*)d_in[4];
    const float* Wm  = (const float*)d_in[5];
    const float* bm  = (const float*)d_in[6];
    float* out = (float*)d_out;

    cudaFuncSetAttribute(gemm_mma_kernel,
                         cudaFuncAttributeMaxDynamicSharedMemorySize, GEMM_SMEM);
    cudaFuncSetAttribute(gru_rec_kernel,
                         cudaFuncAttributeMaxDynamicSharedMemorySize, SM_TOTAL);

    prep_kernel<<<(G3 * EE + 255) / 256, 256>>>(Wz, bz, Wr, br, Wm, bm);
    conv_a_kernel<<<(int)(((size_t)MTOT * EE / 4) / 256), 256>>>(emb);
    gemm_mma_kernel<<<MTOT / 128, 512, GEMM_SMEM>>>();
    gru_rec_kernel<<<128, 256, SM_TOTAL>>>(out);
}

// round 10
// speedup vs baseline: 1.0927x; 1.0115x over previous
#include <cuda_runtime.h>
#include <cuda_fp16.h>
#include <math.h>
#include <stdint.h>

// Problem constants
#define BSZ 256     // batch
#define TT  512     // time steps
#define EE  256     // embedding dim
#define HH  256     // hidden dim
#define KH  512     // E + H
#define G3  768     // 3 * H (z, r, m)
#define MTOT (BSZ * TT)   // 131072 GEMM rows, m = t*256 + b

typedef unsigned long long u64;

// Scratch (device globals: allocation-free rule)
__device__ float   g_bias[G3];
__device__ float2  g_Wzr[HH * HH];              // recurrent z/r interleaved [k][j]
__device__ float   g_Wm2[HH * HH];              // recurrent m [k][j]
__device__ __half  g_Bh [G3 * EE];              // B row n=g*256+j, col k: fp16 of Wg[j][k]
__device__ __half  g_Ahi[(size_t)MTOT * EE];    // A row m=t*256+b: fp16 hi of emb
__device__ __half  g_Alo[(size_t)MTOT * EE];    // fp16 lo residual
__device__ float   g_Gx[(size_t)MTOT * G3];     // x-part + bias, layout [t][b][3H]

// ---------------------------------------------------------------------------
// PTX helpers
// ---------------------------------------------------------------------------
__device__ __forceinline__ u64 pack2(float lo, float hi) {
    u64 r; asm("mov.b64 %0, {%1, %2};" : "=l"(r) : "f"(lo), "f"(hi)); return r;
}
__device__ __forceinline__ float2 unpack2(u64 v) {
    float2 r; asm("mov.b64 {%0, %1}, %2;" : "=f"(r.x), "=f"(r.y) : "l"(v)); return r;
}
__device__ __forceinline__ void ffma2(u64& d, u64 a, u64 b) {
    asm("fma.rn.f32x2 %0, %1, %2, %0;" : "+l"(d) : "l"(a), "l"(b));
}
__device__ __forceinline__ u64 add2(u64 a, u64 b) {
    u64 r; asm("add.rn.f32x2 %0, %1, %2;" : "=l"(r) : "l"(a), "l"(b)); return r;
}
__device__ __forceinline__ uint32_t smem_u32(const void* p) {
    uint32_t a;
    asm("{ .reg .u64 t; cvta.to.shared.u64 t, %1; cvt.u32.u64 %0, t; }" : "=r"(a) : "l"(p));
    return a;
}
__device__ __forceinline__ uint32_t mapa_u32(uint32_t a, uint32_t rank) {
    uint32_t r; asm("mapa.shared::cluster.u32 %0, %1, %2;" : "=r"(r) : "r"(a), "r"(rank)); return r;
}
__device__ __forceinline__ void st_cluster_b64(uint32_t a, u64 v) {
    asm volatile("st.shared::cluster.b64 [%0], %1;" :: "r"(a), "l"(v) : "memory");
}
#define CLUSTER_SYNC() do { \
    asm volatile("barrier.cluster.arrive.aligned;" ::: "memory"); \
    asm volatile("barrier.cluster.wait.aligned;"   ::: "memory"); \
} while (0)

__device__ __forceinline__ float fast_sigmoid(float x) {
    float e = __expf(-x);
    return __fdividef(1.f, 1.f + e);
}
__device__ __forceinline__ float fast_tanh(float x) {
    float e = __expf(2.f * x);
    return __fdividef(e - 1.f, e + 1.f);
}

// ---- warp-level MMA helpers (fp16 inputs, fp32 accum) ----
__device__ __forceinline__ void ldsm_x4(uint32_t* r, uint32_t addr) {
    asm volatile("ldmatrix.sync.aligned.m8n8.x4.shared.b16 {%0,%1,%2,%3}, [%4];"
        : "=r"(r[0]), "=r"(r[1]), "=r"(r[2]), "=r"(r[3]) : "r"(addr));
}
__device__ __forceinline__ void ldsm_x2(uint32_t* r, uint32_t addr) {
    asm volatile("ldmatrix.sync.aligned.m8n8.x2.shared.b16 {%0,%1}, [%2];"
        : "=r"(r[0]), "=r"(r[1]) : "r"(addr));
}
__device__ __forceinline__ void mma16816(float* d, const uint32_t* a, const uint32_t* b) {
    asm volatile(
        "mma.sync.aligned.m16n8k16.row.col.f32.f16.f16.f32 "
        "{%0,%1,%2,%3}, {%4,%5,%6,%7}, {%8,%9}, {%0,%1,%2,%3};"
        : "+f"(d[0]), "+f"(d[1]), "+f"(d[2]), "+f"(d[3])
        : "r"(a[0]), "r"(a[1]), "r"(a[2]), "r"(a[3]), "r"(b[0]), "r"(b[1]));
}

// ---------------------------------------------------------------------------
// Kernel 1: bias + recurrent repack + B fp16 convert
// ---------------------------------------------------------------------------
__global__ void prep_kernel(const float* __restrict__ Wz, const float* __restrict__ bz,
                            const float* __restrict__ Wr, const float* __restrict__ br,
                            const float* __restrict__ Wm, const float* __restrict__ bm) {
    int idx = blockIdx.x * blockDim.x + threadIdx.x;
    if (idx < G3 * EE) {                 // B: row n = g*256+j, col k
        int n = idx >> 8;
        int k = idx & 255;
        int g = n >> 8;
        int j = n & 255;
        const float* W = (g == 0) ? Wz : (g == 1) ? Wr : Wm;
        g_Bh[idx] = __float2half_rn(W[j * KH + k]);
    }
    if (idx < HH * HH) {                 // recurrent repack (k, j)
        int k = idx >> 8;
        int j = idx & 255;
        g_Wzr[idx] = make_float2(Wz[j * KH + EE + k], Wr[j * KH + EE + k]);
        g_Wm2[idx] = Wm[j * KH + EE + k];
    }
    if (idx < G3) {
        int g  = idx >> 8;
        int jj = idx & 255;
        const float* bb = (g == 0) ? bz : (g == 1) ? br : bm;
        g_bias[idx] = bb[jj];
    }
}

// ---------------------------------------------------------------------------
// Kernel 1b: A hi/lo fp16 split (hi+lo reconstruct ~22 mantissa bits)
// ---------------------------------------------------------------------------
__global__ __launch_bounds__(256) void conv_a_kernel(const float* __restrict__ emb) {
    size_t q = (size_t)blockIdx.x * 256 + threadIdx.x;   // quad index
    size_t m = q >> 6;
    int kq = (int)(q & 63) * 4;
    int b = (int)(m & 255);
    int t = (int)(m >> 8);
    float4 v = *(const float4*)(emb + ((size_t)b * TT + t) * EE + kq);
    __half h0 = __float2half_rn(v.x), h1 = __float2half_rn(v.y);
    __half h2 = __float2half_rn(v.z), h3 = __float2half_rn(v.w);
    __half hv[4] = {h0, h1, h2, h3};
    __half lv[4] = {
        __float2half_rn(v.x - __half2float(h0)),
        __float2half_rn(v.y - __half2float(h1)),
        __float2half_rn(v.z - __half2float(h2)),
        __float2half_rn(v.w - __half2float(h3))};
    *(uint2*)(g_Ahi + m * EE + kq) = *(const uint2*)hv;
    *(uint2*)(g_Alo + m * EE + kq) = *(const uint2*)lv;
}

// ---------------------------------------------------------------------------
// Kernel 2: 2-term fp16 GEMM via mma.sync — D = Ahi*B + Alo*B.
// 1024 CTAs x 512 thr (16 warps, 4x4, warp tile 32M x 32N), M-tile 128.
// A (128 x 256, hi+lo) SMEM-resident; B chunks (128n x 128k, fp16 single)
// streamed from L2, 12 rounds.
// ---------------------------------------------------------------------------
#define LDA 264                          // A smem row stride (halves)
#define LDB 136                          // B smem row stride (halves)
#define SA_HI 0
#define SA_LO (128 * LDA * 2)            //  67584
#define SB    (2 * 128 * LDA * 2)        // 135168
#define GEMM_SMEM (SB + 128 * LDB * 2)   // 169984

__global__ void __launch_bounds__(512, 1) gemm_mma_kernel() {
    extern __shared__ char smem[];
    uint32_t sbase = smem_u32(smem);
    int tid  = threadIdx.x;
    int warp = tid >> 5;
    int lane = tid & 31;
    int m0 = blockIdx.x * 128;

    int wm = (warp >> 2) * 32;           // warp M offset
    int wn = (warp & 3) * 32;            // warp N offset

    // ---- Load A tile (full K=256, hi+lo) ----
    for (int u = tid; u < 128 * 32; u += 512) {
        int row = u >> 5;
        int c   = u & 31;
        size_t src = (size_t)(m0 + row) * EE + c * 8;
        int dst = (row * LDA + c * 8) * 2;
        *(uint4*)(smem + SA_HI + dst) = *(const uint4*)(g_Ahi + src);
        *(uint4*)(smem + SA_LO + dst) = *(const uint4*)(g_Alo + src);
    }

    // Fragment lane addressing (verified formulas)
    uint32_t a_row  = (uint32_t)(wm + (lane & 15));
    uint32_t a_coff = (uint32_t)((lane >> 4) * 8);
    uint32_t b_row  = (uint32_t)(wn + (lane & 7));
    uint32_t b_coff = (uint32_t)(((lane >> 3) & 1) * 8);

    for (int nj = 0; nj < 6; nj++) {
        float acc[2][4][4];
#pragma unroll
        for (int mi = 0; mi < 2; mi++)
#pragma unroll
            for (int ni = 0; ni < 4; ni++)
#pragma unroll
                for (int q = 0; q < 4; q++) acc[mi][ni][q] = 0.f;

        for (int kt = 0; kt < 2; kt++) {
            __syncthreads();   // prior reads of B done before overwrite
            // ---- Load B chunk (128n x 128k, fp16) ----
            for (int u = tid; u < 128 * 16; u += 512) {
                int row = u >> 4;
                int c   = u & 15;
                size_t src = (size_t)(nj * 128 + row) * EE + kt * 128 + c * 8;
                int dst = (row * LDB + c * 8) * 2;
                *(uint4*)(smem + SB + dst) = *(const uint4*)(g_Bh + src);
            }
            __syncthreads();

#pragma unroll
            for (int k16 = 0; k16 < 8; k16++) {
                int kA = kt * 128 + k16 * 16;
                int kB = k16 * 16;

                uint32_t aH[2][4], aL[2][4];
#pragma unroll
                for (int mi = 0; mi < 2; mi++) {
                    uint32_t off = ((a_row + mi * 16) * LDA + kA + a_coff) * 2;
                    ldsm_x4(aH[mi], sbase + SA_HI + off);
                    ldsm_x4(aL[mi], sbase + SA_LO + off);
                }
                uint32_t bF[4][2];
#pragma unroll
                for (int ni = 0; ni < 4; ni++) {
                    uint32_t off = ((b_row + ni * 8) * LDB + kB + b_coff) * 2;
                    ldsm_x2(bF[ni], sbase + SB + off);
                }
                // term-ordered: 8 independent MMAs between reuses of each acc
#pragma unroll
                for (int mi = 0; mi < 2; mi++)
#pragma unroll
                    for (int ni = 0; ni < 4; ni++)
                        mma16816(acc[mi][ni], aH[mi], bF[ni]);
#pragma unroll
                for (int mi = 0; mi < 2; mi++)
#pragma unroll
                    for (int ni = 0; ni < 4; ni++)
                        mma16816(acc[mi][ni], aL[mi], bF[ni]);
            }
        }

        // ---- Epilogue: acc + bias -> g_Gx ----
        int row0 = m0 + wm + (lane >> 2);
#pragma unroll
        for (int mi = 0; mi < 2; mi++) {
#pragma unroll
            for (int ni = 0; ni < 4; ni++) {
                int n = nj * 128 + wn + ni * 8 + 2 * (lane & 3);
                float bb0 = __ldg(g_bias + n);
                float bb1 = __ldg(g_bias + n + 1);
                float2 v0 = make_float2(acc[mi][ni][0] + bb0, acc[mi][ni][1] + bb1);
                float2 v1 = make_float2(acc[mi][ni][2] + bb0, acc[mi][ni][3] + bb1);
                *(float2*)(g_Gx + (size_t)(row0 + mi * 16) * G3 + n)     = v0;
                *(float2*)(g_Gx + (size_t)(row0 + mi * 16 + 8) * G3 + n) = v1;
            }
        }
    }
}

// ---------------------------------------------------------------------------
// Kernel 3: recurrent part, cluster-of-4 (R5 version; single change:
// self-rank publish uses local st.shared instead of DSMEM store)
// ---------------------------------------------------------------------------
#define SM_WZR 0
#define SM_WM  131072
#define SM_H   196608
#define SM_RH  204800
#define SM_P   212992
#define SM_TOTAL 231424

__global__ void __launch_bounds__(256, 1) __cluster_dims__(4, 1, 1)
gru_rec_kernel(float* __restrict__ out) {
    extern __shared__ char smem_raw[];
    float2* wzr_s = (float2*)(smem_raw + SM_WZR);
    float*  wm_s  = (float*)(smem_raw + SM_WM);
    float*  h_s   = (float*)(smem_raw + SM_H);
    float*  rh_s  = (float*)(smem_raw + SM_RH);
    u64*    p_s   = (u64*)(smem_raw + SM_P);

    int tid   = threadIdx.x;
    int jl    = tid & 63;
    int ksub  = tid >> 6;
    int crank = blockIdx.x & 3;
    int b0g   = (blockIdx.x >> 2) * 8;
    int jg    = crank * 64 + jl;

    for (int i = tid; i < HH * 64; i += 256) {
        int k  = i >> 6;
        int j2 = (i & 63) + crank * 64;
        wzr_s[i] = g_Wzr[k * HH + j2];
        wm_s[i]  = g_Wm2[k * HH + j2];
    }
    for (int i = tid; i < HH * 8; i += 256) h_s[i] = 0.f;
    __syncthreads();
    CLUSTER_SYNC();

    uint32_t rh_local = smem_u32(rh_s);
    uint32_t h_local  = smem_u32(h_s);
    uint32_t rh_dst[4], h_dst[4];
#pragma unroll
    for (int d = 0; d < 4; d++) {
        rh_dst[d] = mapa_u32(rh_local, (uint32_t)d);
        h_dst[d]  = mapa_u32(h_local,  (uint32_t)d);
    }
    uint32_t off_pair = (uint32_t)(jg * 8 + 2 * ksub) * 4;

    int k0 = ksub * 64;

    for (int t = 0; t < TT; t++) {
        const float* gxb = g_Gx + ((size_t)t * BSZ + b0g + 2 * ksub) * G3 + jg;
        float gz0 = __ldg(gxb);            float gr0 = __ldg(gxb + HH);
        float gm0 = __ldg(gxb + 2 * HH);
        float gz1 = __ldg(gxb + G3);       float gr1 = __ldg(gxb + G3 + HH);
        float gm1 = __ldg(gxb + G3 + 2 * HH);

        u64 az0 = 0, az1 = 0, az2 = 0, az3 = 0;
        u64 ar0 = 0, ar1 = 0, ar2 = 0, ar3 = 0;
#pragma unroll 4
        for (int kk = 0; kk < 64; kk++) {
            int k = k0 + kk;
            float2 w = wzr_s[k * 64 + jl];
            u64 wzz = pack2(w.x, w.x);
            u64 wrr = pack2(w.y, w.y);
            ulonglong2 ha = *(const ulonglong2*)(h_s + k * 8);
            ulonglong2 hb = *(const ulonglong2*)(h_s + k * 8 + 4);
            ffma2(az0, wzz, ha.x); ffma2(az1, wzz, ha.y);
            ffma2(az2, wzz, hb.x); ffma2(az3, wzz, hb.y);
            ffma2(ar0, wrr, ha.x); ffma2(ar1, wrr, ha.y);
            ffma2(ar2, wrr, hb.x); ffma2(ar3, wrr, hb.y);
        }
        {
            u64* pr = p_s + (ksub * 64 + jl) * 9;
            pr[0] = az0; pr[1] = az1; pr[2] = az2; pr[3] = az3;
            pr[4] = ar0; pr[5] = ar1; pr[6] = ar2; pr[7] = ar3;
        }
        __syncthreads();

        u64 zz = 0, rr = 0;
#pragma unroll
        for (int ks = 0; ks < 4; ks++) {
            const u64* pr = p_s + (ks * 64 + jl) * 9;
            zz = add2(zz, pr[ksub]);
            rr = add2(rr, pr[4 + ksub]);
        }
        float2 zf = unpack2(zz), rf = unpack2(rr);
        float z0 = fast_sigmoid(zf.x + gz0);
        float z1 = fast_sigmoid(zf.y + gz1);
        float r0 = fast_sigmoid(rf.x + gr0);
        float r1 = fast_sigmoid(rf.y + gr1);
        float2 hold = *(const float2*)(h_s + jg * 8 + 2 * ksub);
        u64 rhp = pack2(r0 * hold.x, r1 * hold.y);
        *(u64*)((char*)rh_s + off_pair) = rhp;      // local publish
#pragma unroll
        for (int d = 0; d < 4; d++)
            if (d != crank) st_cluster_b64(rh_dst[d] + off_pair, rhp);
        CLUSTER_SYNC();

        u64 am0 = 0, am1 = 0, am2 = 0, am3 = 0;
#pragma unroll 4
        for (int kk = 0; kk < 64; kk++) {
            int k = k0 + kk;
            float wm = wm_s[k * 64 + jl];
            u64 wmm = pack2(wm, wm);
            ulonglong2 ra = *(const ulonglong2*)(rh_s + k * 8);
            ulonglong2 rb = *(const ulonglong2*)(rh_s + k * 8 + 4);
            ffma2(am0, wmm, ra.x); ffma2(am1, wmm, ra.y);
            ffma2(am2, wmm, rb.x); ffma2(am3, wmm, rb.y);
        }
        {
            u64* pr = p_s + (ksub * 64 + jl) * 9;
            pr[0] = am0; pr[1] = am1; pr[2] = am2; pr[3] = am3;
        }
        __syncthreads();

        u64 mm = 0;
#pragma unroll
        for (int ks = 0; ks < 4; ks++)
            mm = add2(mm, p_s[(ks * 64 + jl) * 9 + ksub]);
        float2 mf = unpack2(mm);
        float hc0 = fast_tanh(mf.x + gm0);
        float hc1 = fast_tanh(mf.y + gm1);
        float hn0 = fmaf(z0, hc0 - hold.x, hold.x);
        float hn1 = fmaf(z1, hc1 - hold.y, hold.y);
        u64 hp = pack2(hn0, hn1);
        *(u64*)((char*)h_s + off_pair) = hp;        // local publish
#pragma unroll
        for (int d = 0; d < 4; d++)
            if (d != crank) st_cluster_b64(h_dst[d] + off_pair, hp);

        float* op = out + ((size_t)(b0g + 2 * ksub) * TT + t) * HH + jg;
        op[0]               = hn0;
        op[(size_t)TT * HH] = hn1;
        CLUSTER_SYNC();
    }
}

// ---------------------------------------------------------------------------
// Launch
// ---------------------------------------------------------------------------
extern "C" void kernel_launch(void* const* d_in, const int* in_sizes, int n_in,
                              void* d_out, int out_size) {
    const float* emb = (const float*)d_in[0];
    const float* Wz  = (const float*)d_in[1];
    const float* bz  = (const float*)d_in[2];
    const float* Wr  = (const float*)d_in[3];
    const float* br  = (const float*)d_in[4];
    const float* Wm  = (const float*)d_in[5];
    const float* bm  = (const float*)d_in[6];
    float* out = (float*)d_out;

    cudaFuncSetAttribute(gemm_mma_kernel,
                         cudaFuncAttributeMaxDynamicSharedMemorySize, GEMM_SMEM);
    cudaFuncSetAttribute(gru_rec_kernel,
                         cudaFuncAttributeMaxDynamicSharedMemorySize, SM_TOTAL);

    prep_kernel<<<(G3 * EE + 255) / 256, 256>>>(Wz, bz, Wr, br, Wm, bm);
    conv_a_kernel<<<(int)(((size_t)MTOT * EE / 4) / 256), 256>>>(emb);
    gemm_mma_kernel<<<MTOT / 128, 512, GEMM_SMEM>>>();
    gru_rec_kernel<<<128, 256, SM_TOTAL>>>(out);
}

// round 11
// speedup vs baseline: 1.1635x; 1.0648x over previous
#include <cuda_runtime.h>
#include <cuda_fp16.h>
#include <math.h>
#include <stdint.h>

// Problem constants
#define BSZ 256     // batch
#define TT  512     // time steps
#define EE  256     // embedding dim
#define HH  256     // hidden dim
#define KH  512     // E + H
#define G3  768     // 3 * H (z, r, m)
#define MTOT (BSZ * TT)   // 131072 GEMM rows, m = t*256 + b

typedef unsigned long long u64;

// Scratch (device globals: allocation-free rule)
__device__ float   g_bias[G3];
__device__ float2  g_Wzr[HH * HH];              // recurrent z/r interleaved [k][j]
__device__ float   g_Wm2[HH * HH];              // recurrent m [k][j]
__device__ __half  g_Bh [G3 * EE];              // B row n=g*256+j, col k: fp16 of Wg[j][k]
__device__ __half  g_Ahi[(size_t)MTOT * EE];    // A row m=t*256+b: fp16 hi of emb
__device__ __half  g_Alo[(size_t)MTOT * EE];    // fp16 lo residual
__device__ float   g_Gx[(size_t)MTOT * G3];     // x-part + bias, layout [t][b][3H]

// ---------------------------------------------------------------------------
// PTX helpers
// ---------------------------------------------------------------------------
__device__ __forceinline__ u64 pack2(float lo, float hi) {
    u64 r; asm("mov.b64 %0, {%1, %2};" : "=l"(r) : "f"(lo), "f"(hi)); return r;
}
__device__ __forceinline__ float2 unpack2(u64 v) {
    float2 r; asm("mov.b64 {%0, %1}, %2;" : "=f"(r.x), "=f"(r.y) : "l"(v)); return r;
}
__device__ __forceinline__ void ffma2(u64& d, u64 a, u64 b) {
    asm("fma.rn.f32x2 %0, %1, %2, %0;" : "+l"(d) : "l"(a), "l"(b));
}
__device__ __forceinline__ u64 add2(u64 a, u64 b) {
    u64 r; asm("add.rn.f32x2 %0, %1, %2;" : "=l"(r) : "l"(a), "l"(b)); return r;
}
__device__ __forceinline__ uint32_t smem_u32(const void* p) {
    uint32_t a;
    asm("{ .reg .u64 t; cvta.to.shared.u64 t, %1; cvt.u32.u64 %0, t; }" : "=r"(a) : "l"(p));
    return a;
}
__device__ __forceinline__ uint32_t mapa_u32(uint32_t a, uint32_t rank) {
    uint32_t r; asm("mapa.shared::cluster.u32 %0, %1, %2;" : "=r"(r) : "r"(a), "r"(rank)); return r;
}
// async store to (possibly remote) cluster smem; increments dest CTA's mbarrier
// tx-count by 8 bytes on completion (data-visible before tx signal).
__device__ __forceinline__ void st_async_b64(uint32_t raddr, u64 v, uint32_t rmbar) {
    asm volatile(
        "st.async.weak.shared::cluster.mbarrier::complete_tx::bytes.b64 [%0], %1, [%2];"
        :: "r"(raddr), "l"(v), "r"(rmbar) : "memory");
}
#define MBAR_INIT(mbar, cnt) \
    asm volatile("mbarrier.init.shared.b64 [%0], %1;" :: "r"((uint32_t)(mbar)), "r"((uint32_t)(cnt)) : "memory")
#define MBAR_EXPECT_TX(mbar, bytes) \
    asm volatile("mbarrier.arrive.expect_tx.shared.b64 _, [%0], %1;" \
                 :: "r"((uint32_t)(mbar)), "r"((uint32_t)(bytes)) : "memory")

__device__ __forceinline__ void mbar_wait(uint32_t mbar, uint32_t parity) {
    uint32_t done;
    asm volatile(
        "{\n\t.reg .pred p;\n\t"
        "mbarrier.try_wait.parity.acquire.cta.shared::cta.b64 p, [%1], %2;\n\t"
        "selp.b32 %0, 1, 0, p;\n\t}"
        : "=r"(done) : "r"(mbar), "r"(parity) : "memory");
    if (!done) {
        asm volatile(
            "{\n\t.reg .pred P1;\n\t"
            "WL_%=:\n\t"
            "mbarrier.try_wait.parity.acquire.cta.shared::cta.b64 P1, [%0], %1, 0x989680;\n\t"
            "@P1 bra.uni WD_%=;\n\t"
            "bra.uni WL_%=;\n\t"
            "WD_%=:\n\t}"
            :: "r"(mbar), "r"(parity) : "memory");
    }
}
#define CLUSTER_SYNC() do { \
    asm volatile("barrier.cluster.arrive.aligned;" ::: "memory"); \
    asm volatile("barrier.cluster.wait.aligned;"   ::: "memory"); \
} while (0)

__device__ __forceinline__ float fast_sigmoid(float x) {
    float e = __expf(-x);
    return __fdividef(1.f, 1.f + e);
}
__device__ __forceinline__ float fast_tanh(float x) {
    float e = __expf(2.f * x);
    return __fdividef(e - 1.f, e + 1.f);
}

// ---- warp-level MMA helpers (fp16 inputs, fp32 accum) ----
__device__ __forceinline__ void ldsm_x4(uint32_t* r, uint32_t addr) {
    asm volatile("ldmatrix.sync.aligned.m8n8.x4.shared.b16 {%0,%1,%2,%3}, [%4];"
        : "=r"(r[0]), "=r"(r[1]), "=r"(r[2]), "=r"(r[3]) : "r"(addr));
}
__device__ __forceinline__ void ldsm_x2(uint32_t* r, uint32_t addr) {
    asm volatile("ldmatrix.sync.aligned.m8n8.x2.shared.b16 {%0,%1}, [%2];"
        : "=r"(r[0]), "=r"(r[1]) : "r"(addr));
}
__device__ __forceinline__ void mma16816(float* d, const uint32_t* a, const uint32_t* b) {
    asm volatile(
        "mma.sync.aligned.m16n8k16.row.col.f32.f16.f16.f32 "
        "{%0,%1,%2,%3}, {%4,%5,%6,%7}, {%8,%9}, {%0,%1,%2,%3};"
        : "+f"(d[0]), "+f"(d[1]), "+f"(d[2]), "+f"(d[3])
        : "r"(a[0]), "r"(a[1]), "r"(a[2]), "r"(a[3]), "r"(b[0]), "r"(b[1]));
}

// ---------------------------------------------------------------------------
// Kernel 1: bias + recurrent repack + B fp16 convert
// ---------------------------------------------------------------------------
__global__ void prep_kernel(const float* __restrict__ Wz, const float* __restrict__ bz,
                            const float* __restrict__ Wr, const float* __restrict__ br,
                            const float* __restrict__ Wm, const float* __restrict__ bm) {
    int idx = blockIdx.x * blockDim.x + threadIdx.x;
    if (idx < G3 * EE) {                 // B: row n = g*256+j, col k
        int n = idx >> 8;
        int k = idx & 255;
        int g = n >> 8;
        int j = n & 255;
        const float* W = (g == 0) ? Wz : (g == 1) ? Wr : Wm;
        g_Bh[idx] = __float2half_rn(W[j * KH + k]);
    }
    if (idx < HH * HH) {                 // recurrent repack (k, j)
        int k = idx >> 8;
        int j = idx & 255;
        g_Wzr[idx] = make_float2(Wz[j * KH + EE + k], Wr[j * KH + EE + k]);
        g_Wm2[idx] = Wm[j * KH + EE + k];
    }
    if (idx < G3) {
        int g  = idx >> 8;
        int jj = idx & 255;
        const float* bb = (g == 0) ? bz : (g == 1) ? br : bm;
        g_bias[idx] = bb[jj];
    }
}

// ---------------------------------------------------------------------------
// Kernel 1b: A hi/lo fp16 split
// ---------------------------------------------------------------------------
__global__ __launch_bounds__(256) void conv_a_kernel(const float* __restrict__ emb) {
    size_t q = (size_t)blockIdx.x * 256 + threadIdx.x;   // quad index
    size_t m = q >> 6;
    int kq = (int)(q & 63) * 4;
    int b = (int)(m & 255);
    int t = (int)(m >> 8);
    float4 v = *(const float4*)(emb + ((size_t)b * TT + t) * EE + kq);
    __half h0 = __float2half_rn(v.x), h1 = __float2half_rn(v.y);
    __half h2 = __float2half_rn(v.z), h3 = __float2half_rn(v.w);
    __half hv[4] = {h0, h1, h2, h3};
    __half lv[4] = {
        __float2half_rn(v.x - __half2float(h0)),
        __float2half_rn(v.y - __half2float(h1)),
        __float2half_rn(v.z - __half2float(h2)),
        __float2half_rn(v.w - __half2float(h3))};
    *(uint2*)(g_Ahi + m * EE + kq) = *(const uint2*)hv;
    *(uint2*)(g_Alo + m * EE + kq) = *(const uint2*)lv;
}

// ---------------------------------------------------------------------------
// Kernel 2: 2-term fp16 GEMM via mma.sync (unchanged from R10)
// ---------------------------------------------------------------------------
#define LDA 264                          // A smem row stride (halves)
#define LDB 136                          // B smem row stride (halves)
#define SA_HI 0
#define SA_LO (128 * LDA * 2)            //  67584
#define SB    (2 * 128 * LDA * 2)        // 135168
#define GEMM_SMEM (SB + 128 * LDB * 2)   // 169984

__global__ void __launch_bounds__(512, 1) gemm_mma_kernel() {
    extern __shared__ char smem[];
    uint32_t sbase = smem_u32(smem);
    int tid  = threadIdx.x;
    int warp = tid >> 5;
    int lane = tid & 31;
    int m0 = blockIdx.x * 128;

    int wm = (warp >> 2) * 32;           // warp M offset
    int wn = (warp & 3) * 32;            // warp N offset

    for (int u = tid; u < 128 * 32; u += 512) {
        int row = u >> 5;
        int c   = u & 31;
        size_t src = (size_t)(m0 + row) * EE + c * 8;
        int dst = (row * LDA + c * 8) * 2;
        *(uint4*)(smem + SA_HI + dst) = *(const uint4*)(g_Ahi + src);
        *(uint4*)(smem + SA_LO + dst) = *(const uint4*)(g_Alo + src);
    }

    uint32_t a_row  = (uint32_t)(wm + (lane & 15));
    uint32_t a_coff = (uint32_t)((lane >> 4) * 8);
    uint32_t b_row  = (uint32_t)(wn + (lane & 7));
    uint32_t b_coff = (uint32_t)(((lane >> 3) & 1) * 8);

    for (int nj = 0; nj < 6; nj++) {
        float acc[2][4][4];
#pragma unroll
        for (int mi = 0; mi < 2; mi++)
#pragma unroll
            for (int ni = 0; ni < 4; ni++)
#pragma unroll
                for (int q = 0; q < 4; q++) acc[mi][ni][q] = 0.f;

        for (int kt = 0; kt < 2; kt++) {
            __syncthreads();
            for (int u = tid; u < 128 * 16; u += 512) {
                int row = u >> 4;
                int c   = u & 15;
                size_t src = (size_t)(nj * 128 + row) * EE + kt * 128 + c * 8;
                int dst = (row * LDB + c * 8) * 2;
                *(uint4*)(smem + SB + dst) = *(const uint4*)(g_Bh + src);
            }
            __syncthreads();

#pragma unroll
            for (int k16 = 0; k16 < 8; k16++) {
                int kA = kt * 128 + k16 * 16;
                int kB = k16 * 16;

                uint32_t aH[2][4], aL[2][4];
#pragma unroll
                for (int mi = 0; mi < 2; mi++) {
                    uint32_t off = ((a_row + mi * 16) * LDA + kA + a_coff) * 2;
                    ldsm_x4(aH[mi], sbase + SA_HI + off);
                    ldsm_x4(aL[mi], sbase + SA_LO + off);
                }
                uint32_t bF[4][2];
#pragma unroll
                for (int ni = 0; ni < 4; ni++) {
                    uint32_t off = ((b_row + ni * 8) * LDB + kB + b_coff) * 2;
                    ldsm_x2(bF[ni], sbase + SB + off);
                }
#pragma unroll
                for (int mi = 0; mi < 2; mi++)
#pragma unroll
                    for (int ni = 0; ni < 4; ni++)
                        mma16816(acc[mi][ni], aH[mi], bF[ni]);
#pragma unroll
                for (int mi = 0; mi < 2; mi++)
#pragma unroll
                    for (int ni = 0; ni < 4; ni++)
                        mma16816(acc[mi][ni], aL[mi], bF[ni]);
            }
        }

        int row0 = m0 + wm + (lane >> 2);
#pragma unroll
        for (int mi = 0; mi < 2; mi++) {
#pragma unroll
            for (int ni = 0; ni < 4; ni++) {
                int n = nj * 128 + wn + ni * 8 + 2 * (lane & 3);
                float bb0 = __ldg(g_bias + n);
                float bb1 = __ldg(g_bias + n + 1);
                float2 v0 = make_float2(acc[mi][ni][0] + bb0, acc[mi][ni][1] + bb1);
                float2 v1 = make_float2(acc[mi][ni][2] + bb0, acc[mi][ni][3] + bb1);
                *(float2*)(g_Gx + (size_t)(row0 + mi * 16) * G3 + n)     = v0;
                *(float2*)(g_Gx + (size_t)(row0 + mi * 16 + 8) * G3 + n) = v1;
            }
        }
    }
}

// ---------------------------------------------------------------------------
// Kernel 3: recurrent, cluster-of-4. SINGLE CHANGE vs R10:
// both per-step barrier.cluster replaced by tx-counted mbarriers + st.async.
// Each CTA receives 4 CTAs x 256 thr x 8B = 8192B per exchange; one thread
// posts expect_tx(8192) per barrier per step; all threads wait on parity t&1.
// ---------------------------------------------------------------------------
#define SM_WZR 0
#define SM_WM  131072
#define SM_H   196608
#define SM_RH  204800
#define SM_P   212992
#define SM_BAR 231424              // 2 mbarriers (16B)
#define SM_TOTAL 231456

__global__ void __launch_bounds__(256, 1) __cluster_dims__(4, 1, 1)
gru_rec_kernel(float* __restrict__ out) {
    extern __shared__ char smem_raw[];
    float2* wzr_s = (float2*)(smem_raw + SM_WZR);
    float*  wm_s  = (float*)(smem_raw + SM_WM);
    float*  h_s   = (float*)(smem_raw + SM_H);
    float*  rh_s  = (float*)(smem_raw + SM_RH);
    u64*    p_s   = (u64*)(smem_raw + SM_P);

    int tid   = threadIdx.x;
    int jl    = tid & 63;
    int ksub  = tid >> 6;
    int crank = blockIdx.x & 3;
    int b0g   = (blockIdx.x >> 2) * 8;
    int jg    = crank * 64 + jl;

    for (int i = tid; i < HH * 64; i += 256) {
        int k  = i >> 6;
        int j2 = (i & 63) + crank * 64;
        wzr_s[i] = g_Wzr[k * HH + j2];
        wm_s[i]  = g_Wm2[k * HH + j2];
    }
    for (int i = tid; i < HH * 8; i += 256) h_s[i] = 0.f;

    uint32_t bar_rh = smem_u32(smem_raw + SM_BAR);
    uint32_t bar_h  = bar_rh + 8;
    if (tid == 0) {
        MBAR_INIT(bar_rh, 1);
        MBAR_INIT(bar_h, 1);
    }
    __syncthreads();
    CLUSTER_SYNC();    // barriers + h_s init visible cluster-wide before any st.async

    uint32_t rh_local = smem_u32(rh_s);
    uint32_t h_local  = smem_u32(h_s);
    uint32_t rh_dst[4], h_dst[4], rbar_rh[4], rbar_h[4];
#pragma unroll
    for (int d = 0; d < 4; d++) {
        rh_dst[d]  = mapa_u32(rh_local, (uint32_t)d);
        h_dst[d]   = mapa_u32(h_local,  (uint32_t)d);
        rbar_rh[d] = mapa_u32(bar_rh,   (uint32_t)d);
        rbar_h[d]  = mapa_u32(bar_h,    (uint32_t)d);
    }
    uint32_t off_pair = (uint32_t)(jg * 8 + 2 * ksub) * 4;

    int k0 = ksub * 64;

    for (int t = 0; t < TT; t++) {
        uint32_t par = (uint32_t)(t & 1);
        if (tid == 0) {
            MBAR_EXPECT_TX(bar_rh, 8192);
            MBAR_EXPECT_TX(bar_h, 8192);
        }

        const float* gxb = g_Gx + ((size_t)t * BSZ + b0g + 2 * ksub) * G3 + jg;
        float gz0 = __ldg(gxb);            float gr0 = __ldg(gxb + HH);
        float gm0 = __ldg(gxb + 2 * HH);
        float gz1 = __ldg(gxb + G3);       float gr1 = __ldg(gxb + G3 + HH);
        float gm1 = __ldg(gxb + G3 + 2 * HH);

        u64 az0 = 0, az1 = 0, az2 = 0, az3 = 0;
        u64 ar0 = 0, ar1 = 0, ar2 = 0, ar3 = 0;
#pragma unroll 4
        for (int kk = 0; kk < 64; kk++) {
            int k = k0 + kk;
            float2 w = wzr_s[k * 64 + jl];
            u64 wzz = pack2(w.x, w.x);
            u64 wrr = pack2(w.y, w.y);
            ulonglong2 ha = *(const ulonglong2*)(h_s + k * 8);
            ulonglong2 hb = *(const ulonglong2*)(h_s + k * 8 + 4);
            ffma2(az0, wzz, ha.x); ffma2(az1, wzz, ha.y);
            ffma2(az2, wzz, hb.x); ffma2(az3, wzz, hb.y);
            ffma2(ar0, wrr, ha.x); ffma2(ar1, wrr, ha.y);
            ffma2(ar2, wrr, hb.x); ffma2(ar3, wrr, hb.y);
        }
        {
            u64* pr = p_s + (ksub * 64 + jl) * 9;
            pr[0] = az0; pr[1] = az1; pr[2] = az2; pr[3] = az3;
            pr[4] = ar0; pr[5] = ar1; pr[6] = ar2; pr[7] = ar3;
        }
        __syncthreads();

        u64 zz = 0, rr = 0;
#pragma unroll
        for (int ks = 0; ks < 4; ks++) {
            const u64* pr = p_s + (ks * 64 + jl) * 9;
            zz = add2(zz, pr[ksub]);
            rr = add2(rr, pr[4 + ksub]);
        }
        float2 zf = unpack2(zz), rf = unpack2(rr);
        float z0 = fast_sigmoid(zf.x + gz0);
        float z1 = fast_sigmoid(zf.y + gz1);
        float r0 = fast_sigmoid(rf.x + gr0);
        float r1 = fast_sigmoid(rf.y + gr1);
        float2 hold = *(const float2*)(h_s + jg * 8 + 2 * ksub);
        u64 rhp = pack2(r0 * hold.x, r1 * hold.y);
#pragma unroll
        for (int d = 0; d < 4; d++)
            st_async_b64(rh_dst[d] + off_pair, rhp, rbar_rh[d]);
        mbar_wait(bar_rh, par);

        u64 am0 = 0, am1 = 0, am2 = 0, am3 = 0;
#pragma unroll 4
        for (int kk = 0; kk < 64; kk++) {
            int k = k0 + kk;
            float wm = wm_s[k * 64 + jl];
            u64 wmm = pack2(wm, wm);
            ulonglong2 ra = *(const ulonglong2*)(rh_s + k * 8);
            ulonglong2 rb = *(const ulonglong2*)(rh_s + k * 8 + 4);
            ffma2(am0, wmm, ra.x); ffma2(am1, wmm, ra.y);
            ffma2(am2, wmm, rb.x); ffma2(am3, wmm, rb.y);
        }
        {
            u64* pr = p_s + (ksub * 64 + jl) * 9;
            pr[0] = am0; pr[1] = am1; pr[2] = am2; pr[3] = am3;
        }
        __syncthreads();

        u64 mm = 0;
#pragma unroll
        for (int ks = 0; ks < 4; ks++)
            mm = add2(mm, p_s[(ks * 64 + jl) * 9 + ksub]);
        float2 mf = unpack2(mm);
        float hc0 = fast_tanh(mf.x + gm0);
        float hc1 = fast_tanh(mf.y + gm1);
        float hn0 = fmaf(z0, hc0 - hold.x, hold.x);
        float hn1 = fmaf(z1, hc1 - hold.y, hold.y);
        u64 hp = pack2(hn0, hn1);
#pragma unroll
        for (int d = 0; d < 4; d++)
            st_async_b64(h_dst[d] + off_pair, hp, rbar_h[d]);

        float* op = out + ((size_t)(b0g + 2 * ksub) * TT + t) * HH + jg;
        op[0]               = hn0;
        op[(size_t)TT * HH] = hn1;
        mbar_wait(bar_h, par);
    }
    CLUSTER_SYNC();    // no CTA exits while peers could still target its smem
}

// ---------------------------------------------------------------------------
// Launch
// ---------------------------------------------------------------------------
extern "C" void kernel_launch(void* const* d_in, const int* in_sizes, int n_in,
                              void* d_out, int out_size) {
    const float* emb = (const float*)d_in[0];
    const float* Wz  = (const float*)d_in[1];
    const float* bz  = (const float*)d_in[2];
    const float* Wr  = (const float*)d_in[3];
    const float* br  = (const float*)d_in[4];
    const float* Wm  = (const float*)d_in[5];
    const float* bm  = (const float*)d_in[6];
    float* out = (float*)d_out;

    cudaFuncSetAttribute(gemm_mma_kernel,
                         cudaFuncAttributeMaxDynamicSharedMemorySize, GEMM_SMEM);
    cudaFuncSetAttribute(gru_rec_kernel,
                         cudaFuncAttributeMaxDynamicSharedMemorySize, SM_TOTAL);

    prep_kernel<<<(G3 * EE + 255) / 256, 256>>>(Wz, bz, Wr, br, Wm, bm);
    conv_a_kernel<<<(int)(((size_t)MTOT * EE / 4) / 256), 256>>>(emb);
    gemm_mma_kernel<<<MTOT / 128, 512, GEMM_SMEM>>>();
    gru_rec_kernel<<<128, 256, SM_TOTAL>>>(out);
}